// round 6
// baseline (speedup 1.0000x reference)
#include <cuda_runtime.h>
#include <math.h>
#include <stdint.h>

// Problem constants
#define L_    1024
#define B_    4
#define E_    1024
#define H_    16
#define DK_   64
#define TOPK_ 32
#define M_    (L_ * B_)   // 4096 rows for all GEMMs

// Scratch (no cudaMalloc allowed)
__device__ float g_q[B_ * H_ * L_ * DK_];
__device__ float g_k[B_ * H_ * L_ * DK_];
__device__ float g_v[B_ * H_ * L_ * DK_];
__device__ float g_ctx[L_ * B_ * E_];

// ---------------------------------------------------------------------------
// TF32 tensor-core GEMM: C = A[M,K] @ W[N,K]^T + bias
// Block tile 128x128, BK=16, 8 warps (4 x 2), warp tile 32x64.
// Fragment-native smem layouts:
//   A: As[ks][mq][g][tig] = uint4 {A[mq*16+g][k0+tig], A[mq*16+g+8][k0+tig],
//                                  A[mq*16+g][k0+tig+4], A[mq*16+g+8][k0+tig+4]}
//      -> one LDS.128 per A fragment (lane-sequential, conflict-free)
//   B: Bs[ks][tig][n] = uint2 {B[k0+tig][n], B[k0+tig+4][n]}
//      -> one LDS.64 per B fragment pair (stride 136: 2 lanes/bank-pair = min)
// ---------------------------------------------------------------------------
#define BM    128
#define BN    128
#define BKT   16
#define NKT   (E_ / BKT)   // 64
#define BSTR2 136          // B row stride in uint2 (136 % 16 == 8)

__device__ __forceinline__ uint32_t f2tf32(float f) {
    uint32_t r;
    asm("cvt.rna.tf32.f32 %0, %1;" : "=r"(r) : "f"(f));
    return r;
}

__device__ __forceinline__ void mma_tf32(float (&d)[4],
                                         uint32_t a0, uint32_t a1,
                                         uint32_t a2, uint32_t a3,
                                         uint32_t b0, uint32_t b1) {
    asm volatile(
        "mma.sync.aligned.m16n8k8.row.col.f32.tf32.tf32.f32 "
        "{%0,%1,%2,%3}, {%4,%5,%6,%7}, {%8,%9}, {%0,%1,%2,%3};"
        : "+f"(d[0]), "+f"(d[1]), "+f"(d[2]), "+f"(d[3])
        : "r"(a0), "r"(a1), "r"(a2), "r"(a3), "r"(b0), "r"(b1));
}

// Shared mainloop. acc[mt][nt][4] per-thread.
__device__ __forceinline__ void tf32_mainloop(
    const float* __restrict__ A, const float* __restrict__ W,
    int m0, int n0, float (&acc)[2][8][4],
    uint4 (&As)[2][2][8][8][4], uint2 (&Bs)[2][2][4][BSTR2])
{
    const int tid  = threadIdx.x;
    const int lane = tid & 31;
    const int wid  = tid >> 5;
    const int wm   = wid & 3;    // 0..3 -> rows wm*32
    const int wn   = wid >> 2;   // 0..1 -> cols wn*64
    const int g    = lane >> 2;  // 0..7
    const int tig  = lane & 3;   // 0..3

    // Loader: thread handles row lm of both A-tile and W-tile, two k4-chunks
    const int lm  = tid >> 1;                 // 0..127
    const int ck0 = (tid & 1) * 2;            // chunk base 0 or 2
    const float* Ag = A + (size_t)(m0 + lm) * E_;
    const float* Wg = W + (size_t)(n0 + lm) * E_;

    // Staging coordinates for A elements of row lm
    const int mq   = lm >> 4;        // m/16
    const int gs   = lm & 7;         // g of staged row
    const int posm = (lm >> 3) & 1;  // row in {g, g+8}

    float4 apf[2], bpf[2];

    auto prefetch = [&](int kt) {
#pragma unroll
        for (int it = 0; it < 2; it++) {
            const int kk = (ck0 + it) << 2;
            apf[it] = *(const float4*)(Ag + kt * BKT + kk);
            bpf[it] = *(const float4*)(Wg + kt * BKT + kk);
        }
    };
    auto stage = [&](int buf) {
#pragma unroll
        for (int it = 0; it < 2; it++) {
            const int kk   = (ck0 + it) << 2;  // 0,4,8,12
            const int ks   = kk >> 3;          // k0 half
            const int posk = (kk >> 2) & 1;    // k in {tig, tig+4}
            float a4[4], b4[4];
            *(float4*)a4 = apf[it];
            *(float4*)b4 = bpf[it];
#pragma unroll
            for (int e = 0; e < 4; e++) {
                ((uint32_t*)&As[buf][ks][mq][gs][e])[posm + 2 * posk] = f2tf32(a4[e]);
                ((uint32_t*)&Bs[buf][ks][e][lm])[posk]                = f2tf32(b4[e]);
            }
        }
    };

    // Prologue
    prefetch(0);
    stage(0);
    __syncthreads();
    prefetch(1);

    for (int kt = 0; kt < NKT; kt++) {
        const int cur = kt & 1;
        const int nxt = cur ^ 1;
        if (kt + 1 < NKT) stage(nxt);
        if (kt + 2 < NKT) prefetch(kt + 2);

#pragma unroll
        for (int ks = 0; ks < 2; ks++) {
            const uint4 a0 = As[cur][ks][wm * 2 + 0][g][tig];
            const uint4 a1 = As[cur][ks][wm * 2 + 1][g][tig];
#pragma unroll
            for (int nt = 0; nt < 8; nt++) {
                const uint2 bp = Bs[cur][ks][tig][wn * 64 + nt * 8 + g];
                mma_tf32(acc[0][nt], a0.x, a0.y, a0.z, a0.w, bp.x, bp.y);
                mma_tf32(acc[1][nt], a1.x, a1.y, a1.z, a1.w, bp.x, bp.y);
            }
        }
        __syncthreads();
    }
}

// Fused QKV GEMM: z selects {q,k,v}; epilogue scatters to [B,H,L,DK] + bias (+scale)
__global__ __launch_bounds__(256, 2)
void qkv_mma_kernel(const float* __restrict__ query,
                    const float* __restrict__ key,
                    const float* __restrict__ value,
                    const float* __restrict__ w_in,
                    const float* __restrict__ b_in)
{
    __shared__ uint4 As[2][2][8][8][4];
    __shared__ uint2 Bs[2][2][4][BSTR2];

    const int z = blockIdx.z;
    const float* A    = (z == 0) ? query : (z == 1) ? key : value;
    const float* W    = w_in + (size_t)z * E_ * E_;
    const float* bias = b_in + z * E_;
    float* C          = (z == 0) ? g_q : (z == 1) ? g_k : g_v;
    const float scale = (z == 0) ? 0.125f : 1.0f;  // DK^-0.5

    const int m0 = blockIdx.y * BM;
    const int n0 = blockIdx.x * BN;

    float acc[2][8][4];
#pragma unroll
    for (int mt = 0; mt < 2; mt++)
#pragma unroll
        for (int nt = 0; nt < 8; nt++)
#pragma unroll
            for (int e = 0; e < 4; e++) acc[mt][nt][e] = 0.f;

    tf32_mainloop(A, W, m0, n0, acc, As, Bs);

    const int lane = threadIdx.x & 31;
    const int wid  = threadIdx.x >> 5;
    const int wm   = wid & 3;
    const int wn   = wid >> 2;
    const int g    = lane >> 2;
    const int tig  = lane & 3;

    // Warp covers exactly one head: h = (n0 + wn*64)/64
    const int h = (n0 >> 6) + wn;

#pragma unroll
    for (int mt = 0; mt < 2; mt++) {
        const int mr = m0 + wm * 32 + mt * 16 + g;   // rows mr and mr+8
        const int l0 = mr >> 2;                      // /B_
        const int bb = mr & 3;                       // %B_ (same for mr+8)
        const int l1 = l0 + 2;
        float* base = C + (size_t)(bb * H_ + h) * L_ * DK_;
#pragma unroll
        for (int nt = 0; nt < 8; nt++) {
            const int d  = nt * 8 + tig * 2;         // within-head col (even)
            const int nc = n0 + wn * 64 + d;
            const float bv0 = bias[nc];
            const float bv1 = bias[nc + 1];
            float2 r0 = make_float2((acc[mt][nt][0] + bv0) * scale,
                                    (acc[mt][nt][1] + bv1) * scale);
            float2 r1 = make_float2((acc[mt][nt][2] + bv0) * scale,
                                    (acc[mt][nt][3] + bv1) * scale);
            *(float2*)(base + (size_t)l0 * DK_ + d) = r0;
            *(float2*)(base + (size_t)l1 * DK_ + d) = r1;
        }
    }
}

// Output projection GEMM: plain [M, E] epilogue
__global__ __launch_bounds__(256, 2)
void out_mma_kernel(const float* __restrict__ out_w,
                    const float* __restrict__ out_b,
                    float* __restrict__ C)
{
    __shared__ uint4 As[2][2][8][8][4];
    __shared__ uint2 Bs[2][2][4][BSTR2];

    const int m0 = blockIdx.y * BM;
    const int n0 = blockIdx.x * BN;

    float acc[2][8][4];
#pragma unroll
    for (int mt = 0; mt < 2; mt++)
#pragma unroll
        for (int nt = 0; nt < 8; nt++)
#pragma unroll
            for (int e = 0; e < 4; e++) acc[mt][nt][e] = 0.f;

    tf32_mainloop(g_ctx, out_w, m0, n0, acc, As, Bs);

    const int lane = threadIdx.x & 31;
    const int wid  = threadIdx.x >> 5;
    const int wm   = wid & 3;
    const int wn   = wid >> 2;
    const int g    = lane >> 2;
    const int tig  = lane & 3;

#pragma unroll
    for (int mt = 0; mt < 2; mt++) {
        const int mr = m0 + wm * 32 + mt * 16 + g;
#pragma unroll
        for (int nt = 0; nt < 8; nt++) {
            const int nc = n0 + wn * 64 + nt * 8 + tig * 2;
            const float bv0 = out_b[nc];
            const float bv1 = out_b[nc + 1];
            float2 r0 = make_float2(acc[mt][nt][0] + bv0, acc[mt][nt][1] + bv1);
            float2 r1 = make_float2(acc[mt][nt][2] + bv0, acc[mt][nt][3] + bv1);
            *(float2*)(C + (size_t)mr * E_ + nc)       = r0;
            *(float2*)(C + (size_t)(mr + 8) * E_ + nc) = r1;
        }
    }
}

// ---------------------------------------------------------------------------
// Sparse top-k attention. Block = (l, b), warp h = head h, lane t = topk slot.
// ---------------------------------------------------------------------------
__global__ __launch_bounds__(512)
void attn_kernel(const int* __restrict__ mask, float* __restrict__ attn_avg)
{
    const int l    = blockIdx.x;
    const int b    = blockIdx.y;
    const int h    = threadIdx.x >> 5;
    const int lane = threadIdx.x & 31;

    __shared__ float sq[H_][DK_];
    __shared__ float s_attn[H_][TOPK_];
    __shared__ int   s_idx[H_][TOPK_];

    const float* qrow = g_q + (size_t)(((b * H_ + h) * L_) + l) * DK_;
    sq[h][lane]      = qrow[lane];
    sq[h][lane + 32] = qrow[lane + 32];
    __syncwarp();

    const int idx = mask[(size_t)(((b * H_ + h) * L_) + l) * TOPK_ + lane];
    s_idx[h][lane] = idx;
    const float4* krow = (const float4*)(g_k + (size_t)(((b * H_ + h) * L_) + idx) * DK_);
    const float4* sq4  = (const float4*)sq[h];
    float s = 0.f;
#pragma unroll
    for (int j = 0; j < DK_ / 4; j++) {
        float4 kv = krow[j];
        float4 qv = sq4[j];
        s += kv.x * qv.x + kv.y * qv.y + kv.z * qv.z + kv.w * qv.w;
    }

    float mx = s;
#pragma unroll
    for (int off = 16; off > 0; off >>= 1)
        mx = fmaxf(mx, __shfl_xor_sync(0xFFFFFFFFu, mx, off));
    const float e = expf(s - mx);
    float sum = e;
#pragma unroll
    for (int off = 16; off > 0; off >>= 1)
        sum += __shfl_xor_sync(0xFFFFFFFFu, sum, off);
    const float a = e / sum;
    s_attn[h][lane] = a;
    __syncthreads();

    float acc0 = 0.f, acc1 = 0.f;
#pragma unroll
    for (int t = 0; t < TOPK_; t++) {
        const float at = s_attn[h][t];
        const float* vrow = g_v + (size_t)(((b * H_ + h) * L_) + s_idx[h][t]) * DK_;
        acc0 = fmaf(at, vrow[lane],      acc0);
        acc1 = fmaf(at, vrow[lane + 32], acc1);
    }
    float* crow = g_ctx + (size_t)(l * B_ + b) * E_ + h * DK_;
    crow[lane]      = acc0;
    crow[lane + 32] = acc1;

    if (threadIdx.x < TOPK_) {
        const int t = threadIdx.x;
        float ssum = 0.f;
#pragma unroll
        for (int hh = 0; hh < H_; hh++) ssum += s_attn[hh][t];
        attn_avg[(size_t)(b * L_ + l) * TOPK_ + t] = ssum * (1.f / H_);
    }
}

// ---------------------------------------------------------------------------
extern "C" void kernel_launch(void* const* d_in, const int* in_sizes, int n_in,
                              void* d_out, int out_size)
{
    const float* query = (const float*)d_in[0];
    const float* key   = (const float*)d_in[1];
    const float* value = (const float*)d_in[2];
    const int*   mask  = (const int*)  d_in[3];
    const float* w_in  = (const float*)d_in[4];
    const float* b_in  = (const float*)d_in[5];
    const float* out_w = (const float*)d_in[6];
    const float* out_b = (const float*)d_in[7];
    float* out = (float*)d_out;

    // Fused QKV projections on tensor cores (tf32)
    qkv_mma_kernel<<<dim3(E_ / BN, M_ / BM, 3), 256>>>(query, key, value, w_in, b_in);

    // Sparse attention; attn output segment written directly
    attn_kernel<<<dim3(L_, B_), 512>>>(mask, out + (size_t)L_ * B_ * E_);

    // Output projection on tensor cores (tf32)
    out_mma_kernel<<<dim3(E_ / BN, M_ / BM), 256>>>(out_w, out_b, out);
}

// round 8
// speedup vs baseline: 1.1053x; 1.1053x over previous
#include <cuda_runtime.h>
#include <math.h>
#include <stdint.h>

// Problem constants
#define L_    1024
#define B_    4
#define E_    1024
#define H_    16
#define DK_   64
#define TOPK_ 32
#define M_    (L_ * B_)   // 4096 rows for all GEMMs

// Scratch (no cudaMalloc allowed)
__device__ float g_q[B_ * H_ * L_ * DK_];
__device__ float g_k[B_ * H_ * L_ * DK_];
__device__ float g_v[B_ * H_ * L_ * DK_];
__device__ float g_ctx[L_ * B_ * E_];

// ---------------------------------------------------------------------------
// TF32 tensor-core GEMM: C = A[M,K] @ W[N,K]^T + bias
// Block tile 256x128, BK=8, 8 warps (4 along M x 2 along N), warp tile 64x64.
// Per warp per K-step: 16 A-LDS + 16 B-LDS feed 32 MMAs (1.0 LDS/MMA).
// Smem layouts (R5-proven, conflict-free):
//   As[buf][row][k]  row stride 12 : bank = 12g+tig  (injective over warp)
//   Bs[buf][k][col]  row stride 136: bank = 8tig+g   (injective over warp)
// Staging: A = 2x STS.128 per thread, B = 4x STS.32 per thread.
// ---------------------------------------------------------------------------
#define BMM   256
#define BNN   128
#define BK8   8
#define NKT8  (E_ / BK8)   // 128
#define ASTR  12
#define BSTR  136

__device__ __forceinline__ uint32_t f2tf32(float f) {
    uint32_t r;
    asm("cvt.rna.tf32.f32 %0, %1;" : "=r"(r) : "f"(f));
    return r;
}

__device__ __forceinline__ void mma_tf32(float (&d)[4],
                                         uint32_t a0, uint32_t a1,
                                         uint32_t a2, uint32_t a3,
                                         uint32_t b0, uint32_t b1) {
    asm volatile(
        "mma.sync.aligned.m16n8k8.row.col.f32.tf32.tf32.f32 "
        "{%0,%1,%2,%3}, {%4,%5,%6,%7}, {%8,%9}, {%0,%1,%2,%3};"
        : "+f"(d[0]), "+f"(d[1]), "+f"(d[2]), "+f"(d[3])
        : "r"(a0), "r"(a1), "r"(a2), "r"(a3), "r"(b0), "r"(b1));
}

// Shared mainloop. acc[mq][nt][4] per-thread (warp tile 64x64).
__device__ __forceinline__ void tf32_mainloop(
    const float* __restrict__ A, const float* __restrict__ W,
    int m0, int n0, float (&acc)[4][8][4],
    uint32_t (*As)[BMM][ASTR], uint32_t (*Bs)[BK8][BSTR])
{
    const int tid  = threadIdx.x;
    const int lane = tid & 31;
    const int wid  = tid >> 5;
    const int wm   = wid & 3;    // 0..3 -> rows wm*64
    const int wn   = wid >> 2;   // 0..1 -> cols wn*64
    const int g    = lane >> 2;  // 0..7
    const int tig  = lane & 3;   // 0..3

    // Loaders: A row am = tid (2 float4), B row bn = tid/2, chunk bkk (1 float4)
    const int am  = tid;
    const int bn  = tid >> 1;
    const int bkk = (tid & 1) * 4;
    const float* Ag = A + (size_t)(m0 + am) * E_;
    const float* Wg = W + (size_t)(n0 + bn) * E_ + bkk;

    float4 apf0, apf1, bpf;

    auto prefetch = [&](int kt) {
        apf0 = *(const float4*)(Ag + kt * BK8);
        apf1 = *(const float4*)(Ag + kt * BK8 + 4);
        bpf  = *(const float4*)(Wg + kt * BK8);
    };
    auto stage = [&](int buf) {
        uint4 v0, v1;
        v0.x = f2tf32(apf0.x); v0.y = f2tf32(apf0.y);
        v0.z = f2tf32(apf0.z); v0.w = f2tf32(apf0.w);
        v1.x = f2tf32(apf1.x); v1.y = f2tf32(apf1.y);
        v1.z = f2tf32(apf1.z); v1.w = f2tf32(apf1.w);
        *(uint4*)&As[buf][am][0] = v0;
        *(uint4*)&As[buf][am][4] = v1;
        float b4[4];
        *(float4*)b4 = bpf;
#pragma unroll
        for (int e = 0; e < 4; e++)
            Bs[buf][bkk + e][bn] = f2tf32(b4[e]);
    };

    // Prologue
    prefetch(0);
    stage(0);
    __syncthreads();
    prefetch(1);

    for (int kt = 0; kt < NKT8; kt++) {
        const int cur = kt & 1;
        const int nxt = cur ^ 1;
        if (kt + 1 < NKT8) stage(nxt);
        if (kt + 2 < NKT8) prefetch(kt + 2);

        uint4 a[4];
#pragma unroll
        for (int mq = 0; mq < 4; mq++) {
            const int r = wm * 64 + mq * 16 + g;
            a[mq].x = As[cur][r][tig];
            a[mq].y = As[cur][r + 8][tig];
            a[mq].z = As[cur][r][tig + 4];
            a[mq].w = As[cur][r + 8][tig + 4];
        }
#pragma unroll
        for (int nt = 0; nt < 8; nt++) {
            const int nc = wn * 64 + nt * 8 + g;
            const uint32_t b0 = Bs[cur][tig][nc];
            const uint32_t b1 = Bs[cur][tig + 4][nc];
#pragma unroll
            for (int mq = 0; mq < 4; mq++)
                mma_tf32(acc[mq][nt], a[mq].x, a[mq].y, a[mq].z, a[mq].w, b0, b1);
        }
        __syncthreads();
    }
}

// Fused QKV GEMM: z selects {q,k,v}; epilogue scatters to [B,H,L,DK] + bias (+scale)
__global__ __launch_bounds__(256, 1)
void qkv_mma_kernel(const float* __restrict__ query,
                    const float* __restrict__ key,
                    const float* __restrict__ value,
                    const float* __restrict__ w_in,
                    const float* __restrict__ b_in)
{
    __shared__ uint32_t As[2][BMM][ASTR];
    __shared__ uint32_t Bs[2][BK8][BSTR];

    const int z = blockIdx.z;
    const float* A    = (z == 0) ? query : (z == 1) ? key : value;
    const float* W    = w_in + (size_t)z * E_ * E_;
    const float* bias = b_in + z * E_;
    float* C          = (z == 0) ? g_q : (z == 1) ? g_k : g_v;
    const float scale = (z == 0) ? 0.125f : 1.0f;  // DK^-0.5

    const int m0 = blockIdx.y * BMM;
    const int n0 = blockIdx.x * BNN;

    float acc[4][8][4];
#pragma unroll
    for (int mq = 0; mq < 4; mq++)
#pragma unroll
        for (int nt = 0; nt < 8; nt++)
#pragma unroll
            for (int e = 0; e < 4; e++) acc[mq][nt][e] = 0.f;

    tf32_mainloop(A, W, m0, n0, acc, As, Bs);

    const int lane = threadIdx.x & 31;
    const int wid  = threadIdx.x >> 5;
    const int wm   = wid & 3;
    const int wn   = wid >> 2;
    const int g    = lane >> 2;
    const int tig  = lane & 3;

    // Warp covers exactly one head: h = (n0 + wn*64)/64
    const int h = (n0 >> 6) + wn;

#pragma unroll
    for (int mq = 0; mq < 4; mq++) {
        const int mr = m0 + wm * 64 + mq * 16 + g;   // rows mr and mr+8
        const int l0 = mr >> 2;                      // /B_
        const int bb = mr & 3;                       // %B_ (same for mr+8)
        const int l1 = l0 + 2;
        float* base = C + (size_t)(bb * H_ + h) * L_ * DK_;
#pragma unroll
        for (int nt = 0; nt < 8; nt++) {
            const int d  = nt * 8 + tig * 2;         // within-head col (even)
            const int nc = n0 + wn * 64 + d;
            const float bv0 = bias[nc];
            const float bv1 = bias[nc + 1];
            float2 r0 = make_float2((acc[mq][nt][0] + bv0) * scale,
                                    (acc[mq][nt][1] + bv1) * scale);
            float2 r1 = make_float2((acc[mq][nt][2] + bv0) * scale,
                                    (acc[mq][nt][3] + bv1) * scale);
            *(float2*)(base + (size_t)l0 * DK_ + d) = r0;
            *(float2*)(base + (size_t)l1 * DK_ + d) = r1;
        }
    }
}

// Output projection GEMM: plain [M, E] epilogue
__global__ __launch_bounds__(256, 1)
void out_mma_kernel(const float* __restrict__ out_w,
                    const float* __restrict__ out_b,
                    float* __restrict__ C)
{
    __shared__ uint32_t As[2][BMM][ASTR];
    __shared__ uint32_t Bs[2][BK8][BSTR];

    const int m0 = blockIdx.y * BMM;
    const int n0 = blockIdx.x * BNN;

    float acc[4][8][4];
#pragma unroll
    for (int mq = 0; mq < 4; mq++)
#pragma unroll
        for (int nt = 0; nt < 8; nt++)
#pragma unroll
            for (int e = 0; e < 4; e++) acc[mq][nt][e] = 0.f;

    tf32_mainloop(g_ctx, out_w, m0, n0, acc, As, Bs);

    const int lane = threadIdx.x & 31;
    const int wid  = threadIdx.x >> 5;
    const int wm   = wid & 3;
    const int wn   = wid >> 2;
    const int g    = lane >> 2;
    const int tig  = lane & 3;

#pragma unroll
    for (int mq = 0; mq < 4; mq++) {
        const int mr = m0 + wm * 64 + mq * 16 + g;
#pragma unroll
        for (int nt = 0; nt < 8; nt++) {
            const int nc = n0 + wn * 64 + nt * 8 + tig * 2;
            const float bv0 = out_b[nc];
            const float bv1 = out_b[nc + 1];
            float2 r0 = make_float2(acc[mq][nt][0] + bv0, acc[mq][nt][1] + bv1);
            float2 r1 = make_float2(acc[mq][nt][2] + bv0, acc[mq][nt][3] + bv1);
            *(float2*)(C + (size_t)mr * E_ + nc)       = r0;
            *(float2*)(C + (size_t)(mr + 8) * E_ + nc) = r1;
        }
    }
}

// ---------------------------------------------------------------------------
// Sparse top-k attention. Block = (l, b), warp h = head h, lane t = topk slot.
// ---------------------------------------------------------------------------
__global__ __launch_bounds__(512)
void attn_kernel(const int* __restrict__ mask, float* __restrict__ attn_avg)
{
    const int l    = blockIdx.x;
    const int b    = blockIdx.y;
    const int h    = threadIdx.x >> 5;
    const int lane = threadIdx.x & 31;

    __shared__ float sq[H_][DK_];
    __shared__ float s_attn[H_][TOPK_];
    __shared__ int   s_idx[H_][TOPK_];

    const float* qrow = g_q + (size_t)(((b * H_ + h) * L_) + l) * DK_;
    sq[h][lane]      = qrow[lane];
    sq[h][lane + 32] = qrow[lane + 32];
    __syncwarp();

    const int idx = mask[(size_t)(((b * H_ + h) * L_) + l) * TOPK_ + lane];
    s_idx[h][lane] = idx;
    const float4* krow = (const float4*)(g_k + (size_t)(((b * H_ + h) * L_) + idx) * DK_);
    const float4* sq4  = (const float4*)sq[h];
    float s = 0.f;
#pragma unroll
    for (int j = 0; j < DK_ / 4; j++) {
        float4 kv = krow[j];
        float4 qv = sq4[j];
        s += kv.x * qv.x + kv.y * qv.y + kv.z * qv.z + kv.w * qv.w;
    }

    float mx = s;
#pragma unroll
    for (int off = 16; off > 0; off >>= 1)
        mx = fmaxf(mx, __shfl_xor_sync(0xFFFFFFFFu, mx, off));
    const float e = expf(s - mx);
    float sum = e;
#pragma unroll
    for (int off = 16; off > 0; off >>= 1)
        sum += __shfl_xor_sync(0xFFFFFFFFu, sum, off);
    const float a = e / sum;
    s_attn[h][lane] = a;
    __syncthreads();

    float acc0 = 0.f, acc1 = 0.f;
#pragma unroll
    for (int t = 0; t < TOPK_; t++) {
        const float at = s_attn[h][t];
        const float* vrow = g_v + (size_t)(((b * H_ + h) * L_) + s_idx[h][t]) * DK_;
        acc0 = fmaf(at, vrow[lane],      acc0);
        acc1 = fmaf(at, vrow[lane + 32], acc1);
    }
    float* crow = g_ctx + (size_t)(l * B_ + b) * E_ + h * DK_;
    crow[lane]      = acc0;
    crow[lane + 32] = acc1;

    if (threadIdx.x < TOPK_) {
        const int t = threadIdx.x;
        float ssum = 0.f;
#pragma unroll
        for (int hh = 0; hh < H_; hh++) ssum += s_attn[hh][t];
        attn_avg[(size_t)(b * L_ + l) * TOPK_ + t] = ssum * (1.f / H_);
    }
}

// ---------------------------------------------------------------------------
extern "C" void kernel_launch(void* const* d_in, const int* in_sizes, int n_in,
                              void* d_out, int out_size)
{
    const float* query = (const float*)d_in[0];
    const float* key   = (const float*)d_in[1];
    const float* value = (const float*)d_in[2];
    const int*   mask  = (const int*)  d_in[3];
    const float* w_in  = (const float*)d_in[4];
    const float* b_in  = (const float*)d_in[5];
    const float* out_w = (const float*)d_in[6];
    const float* out_b = (const float*)d_in[7];
    float* out = (float*)d_out;

    // Fused QKV projections on tensor cores (tf32)
    qkv_mma_kernel<<<dim3(E_ / BNN, M_ / BMM, 3), 256>>>(query, key, value, w_in, b_in);

    // Sparse attention; attn output segment written directly
    attn_kernel<<<dim3(L_, B_), 512>>>(mask, out + (size_t)L_ * B_ * E_);

    // Output projection on tensor cores (tf32)
    out_mma_kernel<<<dim3(E_ / BNN, M_ / BMM), 256>>>(out_w, out_b, out);
}

// round 10
// speedup vs baseline: 1.3322x; 1.2053x over previous
#include <cuda_runtime.h>
#include <math.h>
#include <stdint.h>

// Problem constants
#define L_    1024
#define B_    4
#define E_    1024
#define H_    16
#define DK_   64
#define TOPK_ 32
#define M_    (L_ * B_)   // 4096 rows for all GEMMs
#define HG_   4           // heads per attention block

// Scratch (no cudaMalloc allowed)
__device__ float g_q[B_ * H_ * L_ * DK_];
__device__ float g_k[B_ * H_ * L_ * DK_];
__device__ float g_v[B_ * H_ * L_ * DK_];
__device__ float g_ctx[L_ * B_ * E_];
__device__ float g_attn_part[B_ * L_ * (H_ / HG_) * TOPK_];

// ---------------------------------------------------------------------------
// TF32 tensor-core GEMM (R5-proven): C = A[M,K] @ W[N,K]^T + bias
// Block tile 128x128, BK=16, 8 warps (4 x 2), warp tile 32x64.
// Smem: As row stride 20 (bank 20g+tig injective), Bs row stride 136 (8tig+g).
// ---------------------------------------------------------------------------
#define BM   128
#define BN   128
#define BKT  16
#define NKT  (E_ / BKT)   // 64
#define ASTR 20
#define BSTR 136

__device__ __forceinline__ uint32_t f2tf32(float f) {
    uint32_t r;
    asm("cvt.rna.tf32.f32 %0, %1;" : "=r"(r) : "f"(f));
    return r;
}

__device__ __forceinline__ void mma_tf32(float (&d)[4],
                                         const uint32_t (&a)[4],
                                         uint32_t b0, uint32_t b1) {
    asm volatile(
        "mma.sync.aligned.m16n8k8.row.col.f32.tf32.tf32.f32 "
        "{%0,%1,%2,%3}, {%4,%5,%6,%7}, {%8,%9}, {%0,%1,%2,%3};"
        : "+f"(d[0]), "+f"(d[1]), "+f"(d[2]), "+f"(d[3])
        : "r"(a[0]), "r"(a[1]), "r"(a[2]), "r"(a[3]), "r"(b0), "r"(b1));
}

__device__ __forceinline__ void tf32_mainloop(
    const float* __restrict__ A, const float* __restrict__ W,
    int m0, int n0, float (&acc)[2][8][4],
    uint32_t (*As)[BM][ASTR], uint32_t (*Bs)[BKT][BSTR])
{
    const int tid  = threadIdx.x;
    const int lane = tid & 31;
    const int wid  = tid >> 5;
    const int wm   = wid & 3;
    const int wn   = wid >> 2;
    const int g    = lane >> 2;
    const int tig  = lane & 3;

    const int lm  = tid >> 1;
    const int ck0 = (tid & 1) * 2;
    const float* Ag = A + (size_t)(m0 + lm) * E_;
    const float* Wg = W + (size_t)(n0 + lm) * E_;

    float4 apf[2], bpf[2];

    auto prefetch = [&](int kt) {
#pragma unroll
        for (int it = 0; it < 2; it++) {
            const int kk = (ck0 + it) << 2;
            apf[it] = *(const float4*)(Ag + kt * BKT + kk);
            bpf[it] = *(const float4*)(Wg + kt * BKT + kk);
        }
    };
    auto stage = [&](int buf) {
#pragma unroll
        for (int it = 0; it < 2; it++) {
            const int kk = (ck0 + it) << 2;
            uint4 av;
            av.x = f2tf32(apf[it].x); av.y = f2tf32(apf[it].y);
            av.z = f2tf32(apf[it].z); av.w = f2tf32(apf[it].w);
            *(uint4*)&As[buf][lm][kk] = av;
            float bt[4];
            *(float4*)bt = bpf[it];
#pragma unroll
            for (int e = 0; e < 4; e++)
                Bs[buf][kk + e][lm] = f2tf32(bt[e]);
        }
    };

    prefetch(0);
    stage(0);
    __syncthreads();
    prefetch(1);

    for (int kt = 0; kt < NKT; kt++) {
        const int cur = kt & 1;
        const int nxt = cur ^ 1;
        if (kt + 1 < NKT) stage(nxt);
        if (kt + 2 < NKT) prefetch(kt + 2);

#pragma unroll
        for (int ks = 0; ks < 2; ks++) {
            const int k0 = ks * 8;
            uint32_t a[2][4];
#pragma unroll
            for (int mt = 0; mt < 2; mt++) {
                const int mr = wm * 32 + mt * 16 + g;
                a[mt][0] = As[cur][mr][k0 + tig];
                a[mt][1] = As[cur][mr + 8][k0 + tig];
                a[mt][2] = As[cur][mr][k0 + tig + 4];
                a[mt][3] = As[cur][mr + 8][k0 + tig + 4];
            }
#pragma unroll
            for (int nt = 0; nt < 8; nt++) {
                const int nc = wn * 64 + nt * 8 + g;
                const uint32_t b0 = Bs[cur][k0 + tig][nc];
                const uint32_t b1 = Bs[cur][k0 + tig + 4][nc];
                mma_tf32(acc[0][nt], a[0], b0, b1);
                mma_tf32(acc[1][nt], a[1], b0, b1);
            }
        }
        __syncthreads();
    }
}

// Fused QKV GEMM: z selects {q,k,v}; epilogue scatters to [B,H,L,DK] + bias (+scale)
__global__ __launch_bounds__(256, 2)
void qkv_mma_kernel(const float* __restrict__ query,
                    const float* __restrict__ key,
                    const float* __restrict__ value,
                    const float* __restrict__ w_in,
                    const float* __restrict__ b_in)
{
    __shared__ uint32_t As[2][BM][ASTR];
    __shared__ uint32_t Bs[2][BKT][BSTR];

    const int z = blockIdx.z;
    const float* A    = (z == 0) ? query : (z == 1) ? key : value;
    const float* W    = w_in + (size_t)z * E_ * E_;
    const float* bias = b_in + z * E_;
    float* C          = (z == 0) ? g_q : (z == 1) ? g_k : g_v;
    const float scale = (z == 0) ? 0.125f : 1.0f;  // DK^-0.5

    const int m0 = blockIdx.y * BM;
    const int n0 = blockIdx.x * BN;

    float acc[2][8][4];
#pragma unroll
    for (int mt = 0; mt < 2; mt++)
#pragma unroll
        for (int nt = 0; nt < 8; nt++)
#pragma unroll
            for (int e = 0; e < 4; e++) acc[mt][nt][e] = 0.f;

    tf32_mainloop(A, W, m0, n0, acc, As, Bs);

    const int lane = threadIdx.x & 31;
    const int wid  = threadIdx.x >> 5;
    const int wm   = wid & 3;
    const int wn   = wid >> 2;
    const int g    = lane >> 2;
    const int tig  = lane & 3;

    const int h = (n0 >> 6) + wn;   // warp covers exactly one head

#pragma unroll
    for (int mt = 0; mt < 2; mt++) {
        const int mr = m0 + wm * 32 + mt * 16 + g;   // rows mr and mr+8
        const int l0 = mr >> 2;
        const int bb = mr & 3;
        const int l1 = l0 + 2;
        float* base = C + (size_t)(bb * H_ + h) * L_ * DK_;
#pragma unroll
        for (int nt = 0; nt < 8; nt++) {
            const int d  = nt * 8 + tig * 2;
            const int nc = n0 + wn * 64 + d;
            const float bv0 = bias[nc];
            const float bv1 = bias[nc + 1];
            float2 r0 = make_float2((acc[mt][nt][0] + bv0) * scale,
                                    (acc[mt][nt][1] + bv1) * scale);
            float2 r1 = make_float2((acc[mt][nt][2] + bv0) * scale,
                                    (acc[mt][nt][3] + bv1) * scale);
            *(float2*)(base + (size_t)l0 * DK_ + d) = r0;
            *(float2*)(base + (size_t)l1 * DK_ + d) = r1;
        }
    }
}

// Output projection GEMM: plain [M, E] epilogue
__global__ __launch_bounds__(256, 2)
void out_mma_kernel(const float* __restrict__ out_w,
                    const float* __restrict__ out_b,
                    float* __restrict__ C)
{
    __shared__ uint32_t As[2][BM][ASTR];
    __shared__ uint32_t Bs[2][BKT][BSTR];

    const int m0 = blockIdx.y * BM;
    const int n0 = blockIdx.x * BN;

    float acc[2][8][4];
#pragma unroll
    for (int mt = 0; mt < 2; mt++)
#pragma unroll
        for (int nt = 0; nt < 8; nt++)
#pragma unroll
            for (int e = 0; e < 4; e++) acc[mt][nt][e] = 0.f;

    tf32_mainloop(g_ctx, out_w, m0, n0, acc, As, Bs);

    const int lane = threadIdx.x & 31;
    const int wid  = threadIdx.x >> 5;
    const int wm   = wid & 3;
    const int wn   = wid >> 2;
    const int g    = lane >> 2;
    const int tig  = lane & 3;

#pragma unroll
    for (int mt = 0; mt < 2; mt++) {
        const int mr = m0 + wm * 32 + mt * 16 + g;
#pragma unroll
        for (int nt = 0; nt < 8; nt++) {
            const int nc = n0 + wn * 64 + nt * 8 + tig * 2;
            const float bv0 = out_b[nc];
            const float bv1 = out_b[nc + 1];
            float2 r0 = make_float2(acc[mt][nt][0] + bv0, acc[mt][nt][1] + bv1);
            float2 r1 = make_float2(acc[mt][nt][2] + bv0, acc[mt][nt][3] + bv1);
            *(float2*)(C + (size_t)mr * E_ + nc)       = r0;
            *(float2*)(C + (size_t)(mr + 8) * E_ + nc) = r1;
        }
    }
}

// ---------------------------------------------------------------------------
// Sparse top-k attention v2: block = (l, b, head-group of 4), warp = head.
// K rows are staged coalescedly into smem (2 sectors/row vs 32 scattered),
// then scores read via padded LDS. Writes ctx to g_ctx and per-group partial
// attn sums to g_attn_part (deterministic; reduced by attn_avg_kernel).
// ---------------------------------------------------------------------------
#define SKSTR 68   // smem K row stride (floats); 272B rows, 16B aligned

__global__ __launch_bounds__(128)
void attn2_kernel(const int* __restrict__ mask)
{
    const int l    = blockIdx.x;
    const int b    = blockIdx.y;
    const int hg   = blockIdx.z;
    const int wi   = threadIdx.x >> 5;       // 0..3
    const int h    = hg * HG_ + wi;
    const int lane = threadIdx.x & 31;

    __shared__ float sk[HG_][TOPK_][SKSTR];
    __shared__ float sq[HG_][DK_];
    __shared__ float s_attn[HG_][TOPK_];
    __shared__ int   s_idx[HG_][TOPK_];

    const size_t base = (size_t)(b * H_ + h) * L_;

    // Stage q
    const float* qrow = g_q + (base + l) * DK_;
    sq[wi][lane]      = qrow[lane];
    sq[wi][lane + 32] = qrow[lane + 32];

    // Per-lane top-k index
    const int idx = mask[(base + l) * TOPK_ + lane];
    s_idx[wi][lane] = idx;
    __syncwarp();

    // Stage 32 K rows coalescedly: iteration t loads row idx_t, float2/lane
#pragma unroll 4
    for (int t = 0; t < TOPK_; t++) {
        const int row = __shfl_sync(0xFFFFFFFFu, idx, t);
        const float2 kv = *(const float2*)(g_k + (base + row) * DK_ + lane * 2);
        *(float2*)&sk[wi][t][lane * 2] = kv;
    }
    __syncwarp();

    // Scores: lane t owns slot t, reads its staged row from smem
    const float4* skr = (const float4*)sk[wi][lane];
    const float4* sq4 = (const float4*)sq[wi];
    float s = 0.f;
#pragma unroll
    for (int j = 0; j < DK_ / 4; j++) {
        const float4 kv = skr[j];
        const float4 qv = sq4[j];
        s += kv.x * qv.x + kv.y * qv.y + kv.z * qv.z + kv.w * qv.w;
    }

    // Softmax across the 32 lanes (== TOPK)
    float mx = s;
#pragma unroll
    for (int off = 16; off > 0; off >>= 1)
        mx = fmaxf(mx, __shfl_xor_sync(0xFFFFFFFFu, mx, off));
    const float e = expf(s - mx);
    float sum = e;
#pragma unroll
    for (int off = 16; off > 0; off >>= 1)
        sum += __shfl_xor_sync(0xFFFFFFFFu, sum, off);
    const float a = e / sum;
    s_attn[wi][lane] = a;
    __syncwarp();

    // Context: lane owns output dims (lane, lane+32); V rows read coalesced
    float acc0 = 0.f, acc1 = 0.f;
#pragma unroll 4
    for (int t = 0; t < TOPK_; t++) {
        const float at = s_attn[wi][t];
        const float* vrow = g_v + (base + s_idx[wi][t]) * DK_;
        acc0 = fmaf(at, vrow[lane],      acc0);
        acc1 = fmaf(at, vrow[lane + 32], acc1);
    }
    float* crow = g_ctx + (size_t)(l * B_ + b) * E_ + h * DK_;
    crow[lane]      = acc0;
    crow[lane + 32] = acc1;

    // Deterministic partial attn sum over this block's 4 heads
    __syncthreads();
    if (threadIdx.x < TOPK_) {
        const int t = threadIdx.x;
        const float p = s_attn[0][t] + s_attn[1][t] + s_attn[2][t] + s_attn[3][t];
        g_attn_part[((size_t)(b * L_ + l) * (H_ / HG_) + hg) * TOPK_ + t] = p;
    }
}

// Reduce head-group partials -> attn_avg [B, L, TOPK]
__global__ __launch_bounds__(256)
void attn_avg_kernel(float* __restrict__ attn_avg)
{
    const int i = blockIdx.x * blockDim.x + threadIdx.x;   // over B*L*TOPK
    if (i >= B_ * L_ * TOPK_) return;
    const int bl = i / TOPK_;     // b*L + l
    const int t  = i % TOPK_;
    const float* p = g_attn_part + ((size_t)bl * (H_ / HG_)) * TOPK_ + t;
    float s = 0.f;
#pragma unroll
    for (int gq = 0; gq < H_ / HG_; gq++) s += p[gq * TOPK_];
    attn_avg[i] = s * (1.f / H_);
}

// ---------------------------------------------------------------------------
extern "C" void kernel_launch(void* const* d_in, const int* in_sizes, int n_in,
                              void* d_out, int out_size)
{
    const float* query = (const float*)d_in[0];
    const float* key   = (const float*)d_in[1];
    const float* value = (const float*)d_in[2];
    const int*   mask  = (const int*)  d_in[3];
    const float* w_in  = (const float*)d_in[4];
    const float* b_in  = (const float*)d_in[5];
    const float* out_w = (const float*)d_in[6];
    const float* out_b = (const float*)d_in[7];
    float* out = (float*)d_out;

    // Fused QKV projections on tensor cores (tf32)
    qkv_mma_kernel<<<dim3(E_ / BN, M_ / BM, 3), 256>>>(query, key, value, w_in, b_in);

    // Sparse attention with staged K gather
    attn2_kernel<<<dim3(L_, B_, H_ / HG_), 128>>>(mask);

    // Reduce partial attn sums into the second output segment
    attn_avg_kernel<<<(B_ * L_ * TOPK_ + 255) / 256, 256>>>(out + (size_t)L_ * B_ * E_);

    // Output projection on tensor cores (tf32)
    out_mma_kernel<<<dim3(E_ / BN, M_ / BM), 256>>>(out_w, out_b, out);
}

// round 12
// speedup vs baseline: 1.7299x; 1.2986x over previous
#include <cuda_runtime.h>
#include <cuda_fp16.h>
#include <math.h>
#include <stdint.h>

// Problem constants
#define L_    1024
#define B_    4
#define E_    1024
#define H_    16
#define DK_   64
#define TOPK_ 32
#define M_    (L_ * B_)   // 4096 rows for all GEMMs
#define HG_   4           // heads per attention block

// Scratch (no cudaMalloc allowed)
__device__ float g_q[B_ * H_ * L_ * DK_];
__device__ float g_k[B_ * H_ * L_ * DK_];
__device__ float g_v[B_ * H_ * L_ * DK_];
__device__ float g_ctx[L_ * B_ * E_];
__device__ float g_attn_part[B_ * L_ * (H_ / HG_) * TOPK_];

// ---------------------------------------------------------------------------
// FP16 tensor-core GEMM (fp32 accumulate): C = A[M,K] @ W[N,K]^T + bias
// Block tile 128x128, BK=16, 8 warps (4 x 2), warp tile 32x64.
// mma.sync.aligned.m16n8k16.row.col.f32.f16.f16.f32
// Both operands staged K-contiguous as half2 words, row stride 12 words:
// fragment LDS.32 banks = (12g + tig) mod 32, injective over the warp.
// Per warp per K-tile: 8 A-LDS + 16 B-LDS feed 16 k16-MMAs (half of TF32's 48).
// ---------------------------------------------------------------------------
#define BM    128
#define BN    128
#define BKT   16
#define NKT   (E_ / BKT)   // 64
#define RSW   12           // row stride in uint32 words (K=16 halves -> 8 words + 4 pad)

__device__ __forceinline__ uint32_t packh2(float a, float b) {
    const half2 h = __floats2half2_rn(a, b);   // .x (low bits) = a
    return *(const uint32_t*)&h;
}

__device__ __forceinline__ void mma_fp16(float (&d)[4],
                                         const uint32_t (&a)[4],
                                         uint32_t b0, uint32_t b1) {
    asm volatile(
        "mma.sync.aligned.m16n8k16.row.col.f32.f16.f16.f32 "
        "{%0,%1,%2,%3}, {%4,%5,%6,%7}, {%8,%9}, {%0,%1,%2,%3};"
        : "+f"(d[0]), "+f"(d[1]), "+f"(d[2]), "+f"(d[3])
        : "r"(a[0]), "r"(a[1]), "r"(a[2]), "r"(a[3]), "r"(b0), "r"(b1));
}

__device__ __forceinline__ void fp16_mainloop(
    const float* __restrict__ A, const float* __restrict__ W,
    int m0, int n0, float (&acc)[2][8][4],
    uint32_t (*As)[BM][RSW], uint32_t (*Bs)[BN][RSW])
{
    const int tid  = threadIdx.x;
    const int lane = tid & 31;
    const int wid  = tid >> 5;
    const int wm   = wid & 3;
    const int wn   = wid >> 2;
    const int g    = lane >> 2;
    const int tig  = lane & 3;

    // Loader: thread handles row lm of both tiles, half the K range (8 floats)
    const int lm  = tid >> 1;            // 0..127
    const int ck0 = (tid & 1) * 2;       // float4-chunk base: 0 or 2
    const float* Ag = A + (size_t)(m0 + lm) * E_;
    const float* Wg = W + (size_t)(n0 + lm) * E_;

    float4 apf[2], bpf[2];

    auto prefetch = [&](int kt) {
#pragma unroll
        for (int it = 0; it < 2; it++) {
            const int kk = (ck0 + it) << 2;
            apf[it] = *(const float4*)(Ag + kt * BKT + kk);
            bpf[it] = *(const float4*)(Wg + kt * BKT + kk);
        }
    };
    auto stage = [&](int buf) {
        uint4 aw, bw;
        aw.x = packh2(apf[0].x, apf[0].y); aw.y = packh2(apf[0].z, apf[0].w);
        aw.z = packh2(apf[1].x, apf[1].y); aw.w = packh2(apf[1].z, apf[1].w);
        bw.x = packh2(bpf[0].x, bpf[0].y); bw.y = packh2(bpf[0].z, bpf[0].w);
        bw.z = packh2(bpf[1].x, bpf[1].y); bw.w = packh2(bpf[1].z, bpf[1].w);
        // words ck0*2 .. ck0*2+3  (0..3 or 4..7); row base lm*48B is 16B aligned
        *(uint4*)&As[buf][lm][ck0 * 2] = aw;
        *(uint4*)&Bs[buf][lm][ck0 * 2] = bw;
    };

    prefetch(0);
    stage(0);
    __syncthreads();
    prefetch(1);

    for (int kt = 0; kt < NKT; kt++) {
        const int cur = kt & 1;
        const int nxt = cur ^ 1;
        if (kt + 1 < NKT) stage(nxt);
        if (kt + 2 < NKT) prefetch(kt + 2);

        uint32_t a[2][4];
#pragma unroll
        for (int mt = 0; mt < 2; mt++) {
            const int r = wm * 32 + mt * 16 + g;
            a[mt][0] = As[cur][r][tig];          // k = 2tig..2tig+1
            a[mt][1] = As[cur][r + 8][tig];
            a[mt][2] = As[cur][r][tig + 4];      // k = 2tig+8..2tig+9
            a[mt][3] = As[cur][r + 8][tig + 4];
        }
#pragma unroll
        for (int nt = 0; nt < 8; nt++) {
            const int nc = wn * 64 + nt * 8 + g;
            const uint32_t b0 = Bs[cur][nc][tig];
            const uint32_t b1 = Bs[cur][nc][tig + 4];
            mma_fp16(acc[0][nt], a[0], b0, b1);
            mma_fp16(acc[1][nt], a[1], b0, b1);
        }
        __syncthreads();
    }
}

// Fused QKV GEMM: z selects {q,k,v}; epilogue scatters to [B,H,L,DK] + bias (+scale)
__global__ __launch_bounds__(256, 2)
void qkv_mma_kernel(const float* __restrict__ query,
                    const float* __restrict__ key,
                    const float* __restrict__ value,
                    const float* __restrict__ w_in,
                    const float* __restrict__ b_in)
{
    __shared__ uint32_t As[2][BM][RSW];
    __shared__ uint32_t Bs[2][BN][RSW];

    const int z = blockIdx.z;
    const float* A    = (z == 0) ? query : (z == 1) ? key : value;
    const float* W    = w_in + (size_t)z * E_ * E_;
    const float* bias = b_in + z * E_;
    float* C          = (z == 0) ? g_q : (z == 1) ? g_k : g_v;
    const float scale = (z == 0) ? 0.125f : 1.0f;  // DK^-0.5

    const int m0 = blockIdx.y * BM;
    const int n0 = blockIdx.x * BN;

    float acc[2][8][4];
#pragma unroll
    for (int mt = 0; mt < 2; mt++)
#pragma unroll
        for (int nt = 0; nt < 8; nt++)
#pragma unroll
            for (int e = 0; e < 4; e++) acc[mt][nt][e] = 0.f;

    fp16_mainloop(A, W, m0, n0, acc, As, Bs);

    const int lane = threadIdx.x & 31;
    const int wid  = threadIdx.x >> 5;
    const int wm   = wid & 3;
    const int wn   = wid >> 2;
    const int g    = lane >> 2;
    const int tig  = lane & 3;

    const int h = (n0 >> 6) + wn;   // warp covers exactly one head

#pragma unroll
    for (int mt = 0; mt < 2; mt++) {
        const int mr = m0 + wm * 32 + mt * 16 + g;   // rows mr and mr+8
        const int l0 = mr >> 2;
        const int bb = mr & 3;
        const int l1 = l0 + 2;
        float* base = C + (size_t)(bb * H_ + h) * L_ * DK_;
#pragma unroll
        for (int nt = 0; nt < 8; nt++) {
            const int d  = nt * 8 + tig * 2;
            const int nc = n0 + wn * 64 + d;
            const float bv0 = bias[nc];
            const float bv1 = bias[nc + 1];
            float2 r0 = make_float2((acc[mt][nt][0] + bv0) * scale,
                                    (acc[mt][nt][1] + bv1) * scale);
            float2 r1 = make_float2((acc[mt][nt][2] + bv0) * scale,
                                    (acc[mt][nt][3] + bv1) * scale);
            *(float2*)(base + (size_t)l0 * DK_ + d) = r0;
            *(float2*)(base + (size_t)l1 * DK_ + d) = r1;
        }
    }
}

// Output projection GEMM: plain [M, E] epilogue
__global__ __launch_bounds__(256, 2)
void out_mma_kernel(const float* __restrict__ out_w,
                    const float* __restrict__ out_b,
                    float* __restrict__ C)
{
    __shared__ uint32_t As[2][BM][RSW];
    __shared__ uint32_t Bs[2][BN][RSW];

    const int m0 = blockIdx.y * BM;
    const int n0 = blockIdx.x * BN;

    float acc[2][8][4];
#pragma unroll
    for (int mt = 0; mt < 2; mt++)
#pragma unroll
        for (int nt = 0; nt < 8; nt++)
#pragma unroll
            for (int e = 0; e < 4; e++) acc[mt][nt][e] = 0.f;

    fp16_mainloop(g_ctx, out_w, m0, n0, acc, As, Bs);

    const int lane = threadIdx.x & 31;
    const int wid  = threadIdx.x >> 5;
    const int wm   = wid & 3;
    const int wn   = wid >> 2;
    const int g    = lane >> 2;
    const int tig  = lane & 3;

#pragma unroll
    for (int mt = 0; mt < 2; mt++) {
        const int mr = m0 + wm * 32 + mt * 16 + g;
#pragma unroll
        for (int nt = 0; nt < 8; nt++) {
            const int nc = n0 + wn * 64 + nt * 8 + tig * 2;
            const float bv0 = out_b[nc];
            const float bv1 = out_b[nc + 1];
            float2 r0 = make_float2(acc[mt][nt][0] + bv0, acc[mt][nt][1] + bv1);
            float2 r1 = make_float2(acc[mt][nt][2] + bv0, acc[mt][nt][3] + bv1);
            *(float2*)(C + (size_t)mr * E_ + nc)       = r0;
            *(float2*)(C + (size_t)(mr + 8) * E_ + nc) = r1;
        }
    }
}

// ---------------------------------------------------------------------------
// Sparse top-k attention v2 (R10-proven): block = (l, b, head-group of 4).
// K rows staged coalescedly into smem; partial attn sums reduced separately.
// ---------------------------------------------------------------------------
#define SKSTR 68   // smem K row stride (floats)

__global__ __launch_bounds__(128)
void attn2_kernel(const int* __restrict__ mask)
{
    const int l    = blockIdx.x;
    const int b    = blockIdx.y;
    const int hg   = blockIdx.z;
    const int wi   = threadIdx.x >> 5;       // 0..3
    const int h    = hg * HG_ + wi;
    const int lane = threadIdx.x & 31;

    __shared__ float sk[HG_][TOPK_][SKSTR];
    __shared__ float sq[HG_][DK_];
    __shared__ float s_attn[HG_][TOPK_];
    __shared__ int   s_idx[HG_][TOPK_];

    const size_t base = (size_t)(b * H_ + h) * L_;

    const float* qrow = g_q + (base + l) * DK_;
    sq[wi][lane]      = qrow[lane];
    sq[wi][lane + 32] = qrow[lane + 32];

    const int idx = mask[(base + l) * TOPK_ + lane];
    s_idx[wi][lane] = idx;
    __syncwarp();

#pragma unroll 4
    for (int t = 0; t < TOPK_; t++) {
        const int row = __shfl_sync(0xFFFFFFFFu, idx, t);
        const float2 kv = *(const float2*)(g_k + (base + row) * DK_ + lane * 2);
        *(float2*)&sk[wi][t][lane * 2] = kv;
    }
    __syncwarp();

    const float4* skr = (const float4*)sk[wi][lane];
    const float4* sq4 = (const float4*)sq[wi];
    float s = 0.f;
#pragma unroll
    for (int j = 0; j < DK_ / 4; j++) {
        const float4 kv = skr[j];
        const float4 qv = sq4[j];
        s += kv.x * qv.x + kv.y * qv.y + kv.z * qv.z + kv.w * qv.w;
    }

    float mx = s;
#pragma unroll
    for (int off = 16; off > 0; off >>= 1)
        mx = fmaxf(mx, __shfl_xor_sync(0xFFFFFFFFu, mx, off));
    const float e = expf(s - mx);
    float sum = e;
#pragma unroll
    for (int off = 16; off > 0; off >>= 1)
        sum += __shfl_xor_sync(0xFFFFFFFFu, sum, off);
    const float a = e / sum;
    s_attn[wi][lane] = a;
    __syncwarp();

    float acc0 = 0.f, acc1 = 0.f;
#pragma unroll 4
    for (int t = 0; t < TOPK_; t++) {
        const float at = s_attn[wi][t];
        const float* vrow = g_v + (base + s_idx[wi][t]) * DK_;
        acc0 = fmaf(at, vrow[lane],      acc0);
        acc1 = fmaf(at, vrow[lane + 32], acc1);
    }
    float* crow = g_ctx + (size_t)(l * B_ + b) * E_ + h * DK_;
    crow[lane]      = acc0;
    crow[lane + 32] = acc1;

    __syncthreads();
    if (threadIdx.x < TOPK_) {
        const int t = threadIdx.x;
        const float p = s_attn[0][t] + s_attn[1][t] + s_attn[2][t] + s_attn[3][t];
        g_attn_part[((size_t)(b * L_ + l) * (H_ / HG_) + hg) * TOPK_ + t] = p;
    }
}

// Reduce head-group partials -> attn_avg [B, L, TOPK]
__global__ __launch_bounds__(256)
void attn_avg_kernel(float* __restrict__ attn_avg)
{
    const int i = blockIdx.x * blockDim.x + threadIdx.x;   // over B*L*TOPK
    if (i >= B_ * L_ * TOPK_) return;
    const int bl = i / TOPK_;
    const int t  = i % TOPK_;
    const float* p = g_attn_part + ((size_t)bl * (H_ / HG_)) * TOPK_ + t;
    float s = 0.f;
#pragma unroll
    for (int gq = 0; gq < H_ / HG_; gq++) s += p[gq * TOPK_];
    attn_avg[i] = s * (1.f / H_);
}

// ---------------------------------------------------------------------------
extern "C" void kernel_launch(void* const* d_in, const int* in_sizes, int n_in,
                              void* d_out, int out_size)
{
    const float* query = (const float*)d_in[0];
    const float* key   = (const float*)d_in[1];
    const float* value = (const float*)d_in[2];
    const int*   mask  = (const int*)  d_in[3];
    const float* w_in  = (const float*)d_in[4];
    const float* b_in  = (const float*)d_in[5];
    const float* out_w = (const float*)d_in[6];
    const float* out_b = (const float*)d_in[7];
    float* out = (float*)d_out;

    // Fused QKV projections on tensor cores (fp16 inputs, fp32 accumulate)
    qkv_mma_kernel<<<dim3(E_ / BN, M_ / BM, 3), 256>>>(query, key, value, w_in, b_in);

    // Sparse attention with staged K gather
    attn2_kernel<<<dim3(L_, B_, H_ / HG_), 128>>>(mask);

    // Reduce partial attn sums into the second output segment
    attn_avg_kernel<<<(B_ * L_ * TOPK_ + 255) / 256, 256>>>(out + (size_t)L_ * B_ * E_);

    // Output projection on tensor cores (fp16)
    out_mma_kernel<<<dim3(E_ / BN, M_ / BM), 256>>>(out_w, out_b, out);
}